// round 1
// baseline (speedup 1.0000x reference)
#include <cuda_runtime.h>
#include <math.h>

#define BB 4
#define SS 2048
#define DD 1024
#define HH 16
#define DHH 64

// Scratch (allocation-free): q/k/v in [B,H,S,DH] head layout, ctx in [B,S,D]
__device__ float g_q[BB * SS * DD];
__device__ float g_k[BB * SS * DD];
__device__ float g_v[BB * SS * DD];
__device__ float g_ctx[BB * SS * DD];

// ---------------------------------------------------------------------------
// GEMM: C = A @ W^T + bias
//   A [M,K] row-major, W [N,K] row-major (K contiguous in both), bias [N]
//   MODE 0: C[m,n] plain row-major [M,N]
//   MODE 1: C written in head layout [B,H,S,DH] (m = b*S+s, n = h*DH+dh)
// Tile: 128x128, BK=8, 256 threads, 8x8 micro-tile per thread.
// ---------------------------------------------------------------------------
template <int MODE>
__global__ __launch_bounds__(256) void gemm_bias_kernel(
    const float* __restrict__ A, const float* __restrict__ W,
    const float* __restrict__ bias, float* __restrict__ C,
    int M, int N, int K)
{
    __shared__ float As[8][128];
    __shared__ float Ws[8][128];

    const int tid = threadIdx.x;
    const int tx = tid & 15;        // 0..15 -> N direction
    const int ty = tid >> 4;        // 0..15 -> M direction
    const int bm = blockIdx.y * 128;
    const int bn = blockIdx.x * 128;

    // tile-load assignment: each thread loads one float4 of A and one of W
    const int lrow = tid >> 1;          // 0..127
    const int lc4  = (tid & 1) * 4;     // 0 or 4

    const float* Aptr = A + (size_t)(bm + lrow) * K + lc4;
    const float* Wptr = W + (size_t)(bn + lrow) * K + lc4;

    float acc[8][8];
#pragma unroll
    for (int i = 0; i < 8; i++)
#pragma unroll
        for (int j = 0; j < 8; j++) acc[i][j] = 0.0f;

    for (int kt = 0; kt < K; kt += 8) {
        float4 av = *(const float4*)(Aptr + kt);
        float4 wv = *(const float4*)(Wptr + kt);
        As[lc4 + 0][lrow] = av.x;
        As[lc4 + 1][lrow] = av.y;
        As[lc4 + 2][lrow] = av.z;
        As[lc4 + 3][lrow] = av.w;
        Ws[lc4 + 0][lrow] = wv.x;
        Ws[lc4 + 1][lrow] = wv.y;
        Ws[lc4 + 2][lrow] = wv.z;
        Ws[lc4 + 3][lrow] = wv.w;
        __syncthreads();

#pragma unroll
        for (int k = 0; k < 8; k++) {
            float a[8], b[8];
            *(float4*)&a[0] = *(const float4*)&As[k][ty * 8];
            *(float4*)&a[4] = *(const float4*)&As[k][ty * 8 + 4];
            *(float4*)&b[0] = *(const float4*)&Ws[k][tx * 8];
            *(float4*)&b[4] = *(const float4*)&Ws[k][tx * 8 + 4];
#pragma unroll
            for (int i = 0; i < 8; i++)
#pragma unroll
                for (int j = 0; j < 8; j++)
                    acc[i][j] += a[i] * b[j];
        }
        __syncthreads();
    }

#pragma unroll
    for (int i = 0; i < 8; i++) {
        const int m = bm + ty * 8 + i;
#pragma unroll
        for (int j = 0; j < 8; j++) {
            const int n = bn + tx * 8 + j;
            const float v = acc[i][j] + bias[n];
            if (MODE == 0) {
                C[(size_t)m * N + n] = v;
            } else {
                const int bidx = m / SS;
                const int sidx = m % SS;
                const int h    = n / DHH;
                const int dh   = n % DHH;
                C[(((size_t)bidx * HH + h) * SS + sidx) * DHH + dh] = v;
            }
        }
    }
}

// ---------------------------------------------------------------------------
// Flash attention, fp32, causal (mask hardcoded = tril, matching reference).
// Br=Bc=64, 256 threads (16x16), 4x4 micro-tile per thread, online softmax.
// q,k,v in [B,H,S,DH]; writes ctx in [B,S,D].
// ---------------------------------------------------------------------------
__global__ __launch_bounds__(256) void flash_kernel(
    const float* __restrict__ Q, const float* __restrict__ K,
    const float* __restrict__ V, float* __restrict__ ctx)
{
    extern __shared__ float sm[];
    const int LD = DHH + 1;  // 65: padded stride (<=2-way LDS conflicts)
    float* Qs = sm;                // [64][LD]
    float* Ks = Qs + 64 * LD;      // [64][LD]
    float* Vs = Ks + 64 * LD;      // [64][LD]
    float* Ps = Vs + 64 * LD;      // [64][LD]

    const int tid = threadIdx.x;
    const int tx = tid & 15;   // column group (key / dh dim)
    const int ty = tid >> 4;   // row group (query dim)
    const int qb = blockIdx.x;       // query block 0..31
    const int bh = blockIdx.y;       // b*H + h

    const float* Qb = Q + ((size_t)bh * SS + (size_t)qb * 64) * DHH;
    const float* Kb = K + (size_t)bh * SS * DHH;
    const float* Vb = V + (size_t)bh * SS * DHH;

    // load Q tile (64 x 64)
    for (int idx = tid; idx < 64 * 16; idx += 256) {
        const int r = idx >> 4;
        const int c = (idx & 15) * 4;
        float4 v = *(const float4*)(Qb + r * DHH + c);
        Qs[r * LD + c + 0] = v.x;
        Qs[r * LD + c + 1] = v.y;
        Qs[r * LD + c + 2] = v.z;
        Qs[r * LD + c + 3] = v.w;
    }

    float m_run[4], l_run[4], o[4][4];
#pragma unroll
    for (int i = 0; i < 4; i++) {
        m_run[i] = -INFINITY;
        l_run[i] = 0.0f;
#pragma unroll
        for (int j = 0; j < 4; j++) o[i][j] = 0.0f;
    }

    const float scale = 0.125f;  // 1/sqrt(64)

    for (int jb = 0; jb <= qb; jb++) {
        __syncthreads();  // prior-iter Ps/Vs reads (and Q store on iter 0) done
        // load K,V tiles (64 x 64 each)
        for (int idx = tid; idx < 64 * 16; idx += 256) {
            const int r = idx >> 4;
            const int c = (idx & 15) * 4;
            float4 kv = *(const float4*)(Kb + (size_t)(jb * 64 + r) * DHH + c);
            float4 vv = *(const float4*)(Vb + (size_t)(jb * 64 + r) * DHH + c);
            Ks[r * LD + c + 0] = kv.x;
            Ks[r * LD + c + 1] = kv.y;
            Ks[r * LD + c + 2] = kv.z;
            Ks[r * LD + c + 3] = kv.w;
            Vs[r * LD + c + 0] = vv.x;
            Vs[r * LD + c + 1] = vv.y;
            Vs[r * LD + c + 2] = vv.z;
            Vs[r * LD + c + 3] = vv.w;
        }
        __syncthreads();

        // S = Q K^T (4x4 per thread)
        float s[4][4];
#pragma unroll
        for (int i = 0; i < 4; i++)
#pragma unroll
            for (int j = 0; j < 4; j++) s[i][j] = 0.0f;

#pragma unroll 8
        for (int d = 0; d < DHH; d++) {
            float qa[4], kb4[4];
#pragma unroll
            for (int i = 0; i < 4; i++) qa[i] = Qs[(ty * 4 + i) * LD + d];
#pragma unroll
            for (int j = 0; j < 4; j++) kb4[j] = Ks[(tx * 4 + j) * LD + d];
#pragma unroll
            for (int i = 0; i < 4; i++)
#pragma unroll
                for (int j = 0; j < 4; j++)
                    s[i][j] += qa[i] * kb4[j];
        }

        // scale + causal mask (only diagonal block needs masking)
        if (jb == qb) {
#pragma unroll
            for (int i = 0; i < 4; i++) {
                const int qg = qb * 64 + ty * 4 + i;
#pragma unroll
                for (int j = 0; j < 4; j++) {
                    const int kg = jb * 64 + tx * 4 + j;
                    s[i][j] = (kg > qg) ? -1e30f : s[i][j] * scale;
                }
            }
        } else {
#pragma unroll
            for (int i = 0; i < 4; i++)
#pragma unroll
                for (int j = 0; j < 4; j++) s[i][j] *= scale;
        }

        // online softmax (row groups of 16 lanes share a row; shfl within 16)
#pragma unroll
        for (int i = 0; i < 4; i++) {
            float mt = fmaxf(fmaxf(s[i][0], s[i][1]), fmaxf(s[i][2], s[i][3]));
#pragma unroll
            for (int off = 8; off >= 1; off >>= 1)
                mt = fmaxf(mt, __shfl_xor_sync(0xffffffffu, mt, off));
            const float mn = fmaxf(m_run[i], mt);
            const float alpha = __expf(m_run[i] - mn);
            float rs = 0.0f;
#pragma unroll
            for (int j = 0; j < 4; j++) {
                const float p = __expf(s[i][j] - mn);
                s[i][j] = p;
                rs += p;
            }
#pragma unroll
            for (int off = 8; off >= 1; off >>= 1)
                rs += __shfl_xor_sync(0xffffffffu, rs, off);
            l_run[i] = alpha * l_run[i] + rs;
            m_run[i] = mn;
#pragma unroll
            for (int j = 0; j < 4; j++) o[i][j] *= alpha;
        }

        // stage P to smem for the PV gemm
#pragma unroll
        for (int i = 0; i < 4; i++)
#pragma unroll
            for (int j = 0; j < 4; j++)
                Ps[(ty * 4 + i) * LD + (tx * 4 + j)] = s[i][j];
        __syncthreads();

        // O += P @ V
#pragma unroll 8
        for (int k = 0; k < 64; k++) {
            float pv[4], vv[4];
#pragma unroll
            for (int i = 0; i < 4; i++) pv[i] = Ps[(ty * 4 + i) * LD + k];
#pragma unroll
            for (int j = 0; j < 4; j++) vv[j] = Vs[k * LD + tx * 4 + j];
#pragma unroll
            for (int i = 0; i < 4; i++)
#pragma unroll
                for (int j = 0; j < 4; j++)
                    o[i][j] += pv[i] * vv[j];
        }
    }

    // finalize + write ctx [B,S,D]
    const int b = bh / HH;
    const int h = bh % HH;
#pragma unroll
    for (int i = 0; i < 4; i++) {
        const float inv = 1.0f / l_run[i];
        const int rg = qb * 64 + ty * 4 + i;
#pragma unroll
        for (int j = 0; j < 4; j++) {
            const int c = tx * 4 + j;
            ctx[((size_t)b * SS + rg) * DD + h * DHH + c] = o[i][j] * inv;
        }
    }
}

// ---------------------------------------------------------------------------
// Launch
// ---------------------------------------------------------------------------
extern "C" void kernel_launch(void* const* d_in, const int* in_sizes, int n_in,
                              void* d_out, int out_size)
{
    const float* query = (const float*)d_in[0];
    const float* key_i = (const float*)d_in[1];
    const float* value = (const float*)d_in[2];
    // d_in[3] = causal mask (tril) — hardcoded in flash_kernel
    const float* Wq = (const float*)d_in[4];
    const float* bq = (const float*)d_in[5];
    const float* Wk = (const float*)d_in[6];
    const float* bk = (const float*)d_in[7];
    const float* Wv = (const float*)d_in[8];
    const float* bv = (const float*)d_in[9];
    const float* Wo = (const float*)d_in[10];
    const float* bo = (const float*)d_in[11];
    float* out = (float*)d_out;

    float *q, *k, *v, *ctx;
    cudaGetSymbolAddress((void**)&q, g_q);
    cudaGetSymbolAddress((void**)&k, g_k);
    cudaGetSymbolAddress((void**)&v, g_v);
    cudaGetSymbolAddress((void**)&ctx, g_ctx);

    const int M = BB * SS;   // 8192
    const int N = DD;        // 1024
    const int K = DD;        // 1024

    dim3 gblock(256);
    dim3 ggrid(N / 128, M / 128);  // (8, 64)

    gemm_bias_kernel<1><<<ggrid, gblock>>>(query, Wq, bq, q, M, N, K);
    gemm_bias_kernel<1><<<ggrid, gblock>>>(key_i, Wk, bk, k, M, N, K);
    gemm_bias_kernel<1><<<ggrid, gblock>>>(value, Wv, bv, v, M, N, K);

    const int LD = DHH + 1;
    const size_t smem = (size_t)4 * 64 * LD * sizeof(float);  // 66,560 B
    cudaFuncSetAttribute(flash_kernel,
                         cudaFuncAttributeMaxDynamicSharedMemorySize,
                         (int)smem);
    flash_kernel<<<dim3(SS / 64, BB * HH), 256, smem>>>(q, k, v, ctx);

    gemm_bias_kernel<0><<<ggrid, gblock>>>(ctx, Wo, bo, out, M, N, K);
}

// round 3
// speedup vs baseline: 1.6821x; 1.6821x over previous
#include <cuda_runtime.h>
#include <cuda_bf16.h>
#include <math.h>
#include <stdint.h>

#define BB 4
#define SS 2048
#define DD 1024
#define HH 16
#define DHH 64

// ---------------------------------------------------------------------------
// Scratch (allocation-free __device__ globals)
// ---------------------------------------------------------------------------
__device__ float g_q[BB * SS * DD];
__device__ float g_k[BB * SS * DD];
__device__ float g_v[BB * SS * DD];
__device__ float g_ctx[BB * SS * DD];
__device__ __nv_bfloat16 g_xhi[BB * SS * DD];
__device__ __nv_bfloat16 g_xlo[BB * SS * DD];
__device__ __nv_bfloat16 g_whi[DD * DD];
__device__ __nv_bfloat16 g_wlo[DD * DD];

// ---------------------------------------------------------------------------
// helpers
// ---------------------------------------------------------------------------
__device__ __forceinline__ uint32_t smem_u32(const void* p) {
    uint32_t a;
    asm("{ .reg .u64 t; cvta.to.shared.u64 t, %1; cvt.u32.u64 %0, t; }"
        : "=r"(a) : "l"(p));
    return a;
}
__device__ __forceinline__ void cp16(uint32_t sdst, const void* gsrc) {
    asm volatile("cp.async.cg.shared.global [%0], [%1], 16;"
                 :: "r"(sdst), "l"(gsrc));
}
__device__ __forceinline__ void cp_commit() {
    asm volatile("cp.async.commit_group;");
}
template <int N>
__device__ __forceinline__ void cp_wait() {
    asm volatile("cp.async.wait_group %0;" :: "n"(N));
}
__device__ __forceinline__ void mma_bf16(float& c0, float& c1, float& c2, float& c3,
                                         uint32_t a0, uint32_t a1, uint32_t a2, uint32_t a3,
                                         uint32_t b0, uint32_t b1) {
    asm volatile(
        "mma.sync.aligned.m16n8k16.row.col.f32.bf16.bf16.f32 "
        "{%0,%1,%2,%3}, {%4,%5,%6,%7}, {%8,%9}, {%0,%1,%2,%3};"
        : "+f"(c0), "+f"(c1), "+f"(c2), "+f"(c3)
        : "r"(a0), "r"(a1), "r"(a2), "r"(a3), "r"(b0), "r"(b1));
}

// ---------------------------------------------------------------------------
// fp32 -> bf16 hi/lo split (vectorized x4)
// ---------------------------------------------------------------------------
__global__ __launch_bounds__(256) void split_kernel(
    const float* __restrict__ x, __nv_bfloat16* __restrict__ hi,
    __nv_bfloat16* __restrict__ lo, int n4)
{
    int i = blockIdx.x * blockDim.x + threadIdx.x;
    if (i >= n4) return;
    float4 v = ((const float4*)x)[i];
    __nv_bfloat16 h0 = __float2bfloat16_rn(v.x);
    __nv_bfloat16 h1 = __float2bfloat16_rn(v.y);
    __nv_bfloat16 h2 = __float2bfloat16_rn(v.z);
    __nv_bfloat16 h3 = __float2bfloat16_rn(v.w);
    __nv_bfloat16 l0 = __float2bfloat16_rn(v.x - __bfloat162float(h0));
    __nv_bfloat16 l1 = __float2bfloat16_rn(v.y - __bfloat162float(h1));
    __nv_bfloat16 l2 = __float2bfloat16_rn(v.z - __bfloat162float(h2));
    __nv_bfloat16 l3 = __float2bfloat16_rn(v.w - __bfloat162float(h3));
    __nv_bfloat162* hp = (__nv_bfloat162*)(hi + (size_t)i * 4);
    __nv_bfloat162* lp = (__nv_bfloat162*)(lo + (size_t)i * 4);
    hp[0] = __nv_bfloat162(h0, h1);
    hp[1] = __nv_bfloat162(h2, h3);
    lp[0] = __nv_bfloat162(l0, l1);
    lp[1] = __nv_bfloat162(l2, l3);
}

// ---------------------------------------------------------------------------
// mma.sync GEMM: C[M,N] = A[M,K] @ W[N,K]^T + bias (fp32 via bf16 hi/lo 3-term)
// CTA 128x128, BK=32, 8 warps (2M x 4N), warp tile 64x32, cp.async 2-stage.
// SMEM tile layout: row-major, row stride 40 bf16 (80B) -> conflict-free b32
// fragment loads. MODE 0: row-major C. MODE 1: head layout [B,H,S,DH].
// ---------------------------------------------------------------------------
#define BK 32
#define NKC (DD / BK)              // 32 chunks
#define TSTRIDE 40                 // bf16 elements per smem row
#define TILE_B (128 * TSTRIDE * 2) // 10240 bytes per tile
#define STAGE_B (4 * TILE_B)       // Ahi,Alo,Whi,Wlo = 40960
#define GEMM_SMEM (2 * STAGE_B)    // 81920

__device__ __forceinline__ void load_tile_async(
    uint32_t sbase, const __nv_bfloat16* __restrict__ src,
    int row_base, int k0, int tid)
{
#pragma unroll
    for (int p = 0; p < 2; p++) {
        const int i = p * 256 + tid;    // 0..511
        const int r = i >> 2;           // 0..127
        const int c = i & 3;            // 16B unit (8 bf16)
        cp16(sbase + r * (TSTRIDE * 2) + c * 16,
             src + (size_t)(row_base + r) * DD + k0 + c * 8);
    }
}

template <int MODE>
__global__ __launch_bounds__(256) void mma_gemm_kernel(
    const __nv_bfloat16* __restrict__ Ahi, const __nv_bfloat16* __restrict__ Alo,
    const __nv_bfloat16* __restrict__ Whi, const __nv_bfloat16* __restrict__ Wlo,
    const float* __restrict__ bias, float* __restrict__ C)
{
    extern __shared__ char sm[];
    const uint32_t sb = smem_u32(sm);
    const int tid = threadIdx.x;
    const int wid = tid >> 5;
    const int lid = tid & 31;
    const int g = lid >> 2;     // group row 0..7
    const int t = lid & 3;      // thread-in-group 0..3
    const int bm = blockIdx.y * 128;
    const int bn = blockIdx.x * 128;
    const int wm = (wid & 1) * 64;   // warp M offset (2 groups)
    const int wn = (wid >> 1) * 32;  // warp N offset (4 groups)

    float acc[4][4][4];
#pragma unroll
    for (int mt = 0; mt < 4; mt++)
#pragma unroll
        for (int nt = 0; nt < 4; nt++)
#pragma unroll
            for (int r = 0; r < 4; r++) acc[mt][nt][r] = 0.0f;

    // prefetch chunk 0 -> stage 0
    {
        const uint32_t s0 = sb;
        load_tile_async(s0 + 0 * TILE_B, Ahi, bm, 0, tid);
        load_tile_async(s0 + 1 * TILE_B, Alo, bm, 0, tid);
        load_tile_async(s0 + 2 * TILE_B, Whi, bn, 0, tid);
        load_tile_async(s0 + 3 * TILE_B, Wlo, bn, 0, tid);
        cp_commit();
    }

    for (int kc = 0; kc < NKC; kc++) {
        const int s = kc & 1;
        if (kc + 1 < NKC) {
            const uint32_t sn = sb + (s ^ 1) * STAGE_B;
            const int k0 = (kc + 1) * BK;
            load_tile_async(sn + 0 * TILE_B, Ahi, bm, k0, tid);
            load_tile_async(sn + 1 * TILE_B, Alo, bm, k0, tid);
            load_tile_async(sn + 2 * TILE_B, Whi, bn, k0, tid);
            load_tile_async(sn + 3 * TILE_B, Wlo, bn, k0, tid);
            cp_commit();
            cp_wait<1>();
        } else {
            cp_wait<0>();
        }
        __syncthreads();

        const char* stg = sm + s * STAGE_B;
        const char* tAhi = stg + 0 * TILE_B;
        const char* tAlo = stg + 1 * TILE_B;
        const char* tWhi = stg + 2 * TILE_B;
        const char* tWlo = stg + 3 * TILE_B;

#pragma unroll
        for (int k16 = 0; k16 < 2; k16++) {
            const int k0 = k16 * 16;
            uint32_t ah[4][4], al[4][4], bh[4][2], bl[4][2];
#pragma unroll
            for (int mt = 0; mt < 4; mt++) {
                const int r0 = wm + mt * 16 + g;
                const int cA = k0 + 2 * t;
                ah[mt][0] = *(const uint32_t*)(tAhi + ((r0)     * TSTRIDE + cA)     * 2);
                ah[mt][1] = *(const uint32_t*)(tAhi + ((r0 + 8) * TSTRIDE + cA)     * 2);
                ah[mt][2] = *(const uint32_t*)(tAhi + ((r0)     * TSTRIDE + cA + 8) * 2);
                ah[mt][3] = *(const uint32_t*)(tAhi + ((r0 + 8) * TSTRIDE + cA + 8) * 2);
                al[mt][0] = *(const uint32_t*)(tAlo + ((r0)     * TSTRIDE + cA)     * 2);
                al[mt][1] = *(const uint32_t*)(tAlo + ((r0 + 8) * TSTRIDE + cA)     * 2);
                al[mt][2] = *(const uint32_t*)(tAlo + ((r0)     * TSTRIDE + cA + 8) * 2);
                al[mt][3] = *(const uint32_t*)(tAlo + ((r0 + 8) * TSTRIDE + cA + 8) * 2);
            }
#pragma unroll
            for (int nt = 0; nt < 4; nt++) {
                const int nr = wn + nt * 8 + g;
                const int cB = k0 + 2 * t;
                bh[nt][0] = *(const uint32_t*)(tWhi + (nr * TSTRIDE + cB)     * 2);
                bh[nt][1] = *(const uint32_t*)(tWhi + (nr * TSTRIDE + cB + 8) * 2);
                bl[nt][0] = *(const uint32_t*)(tWlo + (nr * TSTRIDE + cB)     * 2);
                bl[nt][1] = *(const uint32_t*)(tWlo + (nr * TSTRIDE + cB + 8) * 2);
            }
#pragma unroll
            for (int mt = 0; mt < 4; mt++)
#pragma unroll
                for (int nt = 0; nt < 4; nt++) {
                    float* c = acc[mt][nt];
                    mma_bf16(c[0], c[1], c[2], c[3],
                             ah[mt][0], ah[mt][1], ah[mt][2], ah[mt][3],
                             bh[nt][0], bh[nt][1]);
                    mma_bf16(c[0], c[1], c[2], c[3],
                             ah[mt][0], ah[mt][1], ah[mt][2], ah[mt][3],
                             bl[nt][0], bl[nt][1]);
                    mma_bf16(c[0], c[1], c[2], c[3],
                             al[mt][0], al[mt][1], al[mt][2], al[mt][3],
                             bh[nt][0], bh[nt][1]);
                }
        }
        __syncthreads();
    }

    // epilogue: write C + bias
#pragma unroll
    for (int mt = 0; mt < 4; mt++) {
#pragma unroll
        for (int nt = 0; nt < 4; nt++) {
            const float* c = acc[mt][nt];
            const int n0 = bn + wn + nt * 8 + 2 * t;
            const float bia0 = __ldg(&bias[n0]);
            const float bia1 = __ldg(&bias[n0 + 1]);
#pragma unroll
            for (int half = 0; half < 2; half++) {
                const int m = bm + wm + mt * 16 + g + half * 8;
                const float v0 = c[half * 2 + 0] + bia0;
                const float v1 = c[half * 2 + 1] + bia1;
                if (MODE == 0) {
                    C[(size_t)m * DD + n0] = v0;
                    C[(size_t)m * DD + n0 + 1] = v1;
                } else {
                    const int bidx = m >> 11;          // m / SS
                    const int sidx = m & (SS - 1);
                    const int h0 = n0 >> 6;
                    const int dh0 = n0 & (DHH - 1);
                    // n0 is even and DHH=64, so n0 and n0+1 share h
                    float* dst = &g_ctx[0];  // placeholder (unused)
                    (void)dst;
                    C[(((size_t)bidx * HH + h0) * SS + sidx) * DHH + dh0] = v0;
                    C[(((size_t)bidx * HH + h0) * SS + sidx) * DHH + dh0 + 1] = v1;
                }
            }
        }
    }
}

// ---------------------------------------------------------------------------
// Flash attention (fp32, causal, Br=Bc=64, 256 thr) — unchanged from R1
// ---------------------------------------------------------------------------
__global__ __launch_bounds__(256) void flash_kernel(
    const float* __restrict__ Q, const float* __restrict__ K,
    const float* __restrict__ V, float* __restrict__ ctx)
{
    extern __shared__ float smf[];
    const int LD = DHH + 1;
    float* Qs = smf;
    float* Ks = Qs + 64 * LD;
    float* Vs = Ks + 64 * LD;
    float* Ps = Vs + 64 * LD;

    const int tid = threadIdx.x;
    const int tx = tid & 15;
    const int ty = tid >> 4;
    const int qb = blockIdx.x;
    const int bh = blockIdx.y;

    const float* Qb = Q + ((size_t)bh * SS + (size_t)qb * 64) * DHH;
    const float* Kb = K + (size_t)bh * SS * DHH;
    const float* Vb = V + (size_t)bh * SS * DHH;

    for (int idx = tid; idx < 64 * 16; idx += 256) {
        const int r = idx >> 4;
        const int c = (idx & 15) * 4;
        float4 v = *(const float4*)(Qb + r * DHH + c);
        Qs[r * LD + c + 0] = v.x;
        Qs[r * LD + c + 1] = v.y;
        Qs[r * LD + c + 2] = v.z;
        Qs[r * LD + c + 3] = v.w;
    }

    float m_run[4], l_run[4], o[4][4];
#pragma unroll
    for (int i = 0; i < 4; i++) {
        m_run[i] = -INFINITY;
        l_run[i] = 0.0f;
#pragma unroll
        for (int j = 0; j < 4; j++) o[i][j] = 0.0f;
    }

    const float scale = 0.125f;

    for (int jb = 0; jb <= qb; jb++) {
        __syncthreads();
        for (int idx = tid; idx < 64 * 16; idx += 256) {
            const int r = idx >> 4;
            const int c = (idx & 15) * 4;
            float4 kv = *(const float4*)(Kb + (size_t)(jb * 64 + r) * DHH + c);
            float4 vv = *(const float4*)(Vb + (size_t)(jb * 64 + r) * DHH + c);
            Ks[r * LD + c + 0] = kv.x;
            Ks[r * LD + c + 1] = kv.y;
            Ks[r * LD + c + 2] = kv.z;
            Ks[r * LD + c + 3] = kv.w;
            Vs[r * LD + c + 0] = vv.x;
            Vs[r * LD + c + 1] = vv.y;
            Vs[r * LD + c + 2] = vv.z;
            Vs[r * LD + c + 3] = vv.w;
        }
        __syncthreads();

        float s[4][4];
#pragma unroll
        for (int i = 0; i < 4; i++)
#pragma unroll
            for (int j = 0; j < 4; j++) s[i][j] = 0.0f;

#pragma unroll 8
        for (int d = 0; d < DHH; d++) {
            float qa[4], kb4[4];
#pragma unroll
            for (int i = 0; i < 4; i++) qa[i] = Qs[(ty * 4 + i) * LD + d];
#pragma unroll
            for (int j = 0; j < 4; j++) kb4[j] = Ks[(tx * 4 + j) * LD + d];
#pragma unroll
            for (int i = 0; i < 4; i++)
#pragma unroll
                for (int j = 0; j < 4; j++)
                    s[i][j] += qa[i] * kb4[j];
        }

        if (jb == qb) {
#pragma unroll
            for (int i = 0; i < 4; i++) {
                const int qg = qb * 64 + ty * 4 + i;
#pragma unroll
                for (int j = 0; j < 4; j++) {
                    const int kg = jb * 64 + tx * 4 + j;
                    s[i][j] = (kg > qg) ? -1e30f : s[i][j] * scale;
                }
            }
        } else {
#pragma unroll
            for (int i = 0; i < 4; i++)
#pragma unroll
                for (int j = 0; j < 4; j++) s[i][j] *= scale;
        }

#pragma unroll
        for (int i = 0; i < 4; i++) {
            float mt = fmaxf(fmaxf(s[i][0], s[i][1]), fmaxf(s[i][2], s[i][3]));
#pragma unroll
            for (int off = 8; off >= 1; off >>= 1)
                mt = fmaxf(mt, __shfl_xor_sync(0xffffffffu, mt, off));
            const float mn = fmaxf(m_run[i], mt);
            const float alpha = __expf(m_run[i] - mn);
            float rs = 0.0f;
#pragma unroll
            for (int j = 0; j < 4; j++) {
                const float p = __expf(s[i][j] - mn);
                s[i][j] = p;
                rs += p;
            }
#pragma unroll
            for (int off = 8; off >= 1; off >>= 1)
                rs += __shfl_xor_sync(0xffffffffu, rs, off);
            l_run[i] = alpha * l_run[i] + rs;
            m_run[i] = mn;
#pragma unroll
            for (int j = 0; j < 4; j++) o[i][j] *= alpha;
        }

#pragma unroll
        for (int i = 0; i < 4; i++)
#pragma unroll
            for (int j = 0; j < 4; j++)
                Ps[(ty * 4 + i) * LD + (tx * 4 + j)] = s[i][j];
        __syncthreads();

#pragma unroll 8
        for (int k = 0; k < 64; k++) {
            float pv[4], vv[4];
#pragma unroll
            for (int i = 0; i < 4; i++) pv[i] = Ps[(ty * 4 + i) * LD + k];
#pragma unroll
            for (int j = 0; j < 4; j++) vv[j] = Vs[k * LD + tx * 4 + j];
#pragma unroll
            for (int i = 0; i < 4; i++)
#pragma unroll
                for (int j = 0; j < 4; j++)
                    o[i][j] += pv[i] * vv[j];
        }
    }

    const int b = bh / HH;
    const int h = bh % HH;
#pragma unroll
    for (int i = 0; i < 4; i++) {
        const float inv = 1.0f / l_run[i];
        const int rg = qb * 64 + ty * 4 + i;
#pragma unroll
        for (int j = 0; j < 4; j++) {
            const int c = tx * 4 + j;
            ctx[((size_t)b * SS + rg) * DD + h * DHH + c] = o[i][j] * inv;
        }
    }
}

// ---------------------------------------------------------------------------
// Launch
// ---------------------------------------------------------------------------
extern "C" void kernel_launch(void* const* d_in, const int* in_sizes, int n_in,
                              void* d_out, int out_size)
{
    const float* query = (const float*)d_in[0];
    const float* key_i = (const float*)d_in[1];
    const float* value = (const float*)d_in[2];
    const float* Wq = (const float*)d_in[4];
    const float* bq = (const float*)d_in[5];
    const float* Wk = (const float*)d_in[6];
    const float* bk = (const float*)d_in[7];
    const float* Wv = (const float*)d_in[8];
    const float* bv = (const float*)d_in[9];
    const float* Wo = (const float*)d_in[10];
    const float* bo = (const float*)d_in[11];
    float* out = (float*)d_out;

    float *q, *k, *v, *ctx;
    __nv_bfloat16 *xhi, *xlo, *whi, *wlo;
    cudaGetSymbolAddress((void**)&q, g_q);
    cudaGetSymbolAddress((void**)&k, g_k);
    cudaGetSymbolAddress((void**)&v, g_v);
    cudaGetSymbolAddress((void**)&ctx, g_ctx);
    cudaGetSymbolAddress((void**)&xhi, g_xhi);
    cudaGetSymbolAddress((void**)&xlo, g_xlo);
    cudaGetSymbolAddress((void**)&whi, g_whi);
    cudaGetSymbolAddress((void**)&wlo, g_wlo);

    const int M = BB * SS;  // 8192
    const int nX4 = M * DD / 4;
    const int nW4 = DD * DD / 4;
    dim3 sgX((nX4 + 255) / 256), sgW((nW4 + 255) / 256);
    dim3 ggrid(DD / 128, M / 128);  // (8, 64)

    cudaFuncSetAttribute(mma_gemm_kernel<0>,
                         cudaFuncAttributeMaxDynamicSharedMemorySize, GEMM_SMEM);
    cudaFuncSetAttribute(mma_gemm_kernel<1>,
                         cudaFuncAttributeMaxDynamicSharedMemorySize, GEMM_SMEM);

    // Q projection
    split_kernel<<<sgX, 256>>>(query, xhi, xlo, nX4);
    split_kernel<<<sgW, 256>>>(Wq, whi, wlo, nW4);
    mma_gemm_kernel<1><<<ggrid, 256, GEMM_SMEM>>>(xhi, xlo, whi, wlo, bq, q);
    // K projection
    split_kernel<<<sgX, 256>>>(key_i, xhi, xlo, nX4);
    split_kernel<<<sgW, 256>>>(Wk, whi, wlo, nW4);
    mma_gemm_kernel<1><<<ggrid, 256, GEMM_SMEM>>>(xhi, xlo, whi, wlo, bk, k);
    // V projection
    split_kernel<<<sgX, 256>>>(value, xhi, xlo, nX4);
    split_kernel<<<sgW, 256>>>(Wv, whi, wlo, nW4);
    mma_gemm_kernel<1><<<ggrid, 256, GEMM_SMEM>>>(xhi, xlo, whi, wlo, bv, v);

    // attention
    const int LD = DHH + 1;
    const size_t fsmem = (size_t)4 * 64 * LD * sizeof(float);
    cudaFuncSetAttribute(flash_kernel,
                         cudaFuncAttributeMaxDynamicSharedMemorySize, (int)fsmem);
    flash_kernel<<<dim3(SS / 64, BB * HH), 256, fsmem>>>(q, k, v, ctx);

    // O projection
    split_kernel<<<sgX, 256>>>(ctx, xhi, xlo, nX4);
    split_kernel<<<sgW, 256>>>(Wo, whi, wlo, nW4);
    mma_gemm_kernel<0><<<ggrid, 256, GEMM_SMEM>>>(xhi, xlo, whi, wlo, bo, out);
}

// round 4
// speedup vs baseline: 2.9212x; 1.7366x over previous
#include <cuda_runtime.h>
#include <cuda_bf16.h>
#include <math.h>
#include <stdint.h>

#define BB 4
#define SS 2048
#define DD 1024
#define HH 16
#define DHH 64

// ---------------------------------------------------------------------------
// Scratch (allocation-free __device__ globals)
// ---------------------------------------------------------------------------
__device__ float g_ctx[BB * SS * DD];
__device__ __nv_bfloat16 g_xhi[BB * SS * DD];
__device__ __nv_bfloat16 g_xlo[BB * SS * DD];
__device__ __nv_bfloat16 g_whi[DD * DD];
__device__ __nv_bfloat16 g_wlo[DD * DD];
// attention operands, bf16 hi/lo
__device__ __nv_bfloat16 g_qhi[BB * SS * DD];  // [B,H,S,DH]
__device__ __nv_bfloat16 g_qlo[BB * SS * DD];
__device__ __nv_bfloat16 g_khi[BB * SS * DD];  // [B,H,S,DH]
__device__ __nv_bfloat16 g_klo[BB * SS * DD];
__device__ __nv_bfloat16 g_vthi[BB * SS * DD]; // [B,H,DH,S] (transposed)
__device__ __nv_bfloat16 g_vtlo[BB * SS * DD];

// ---------------------------------------------------------------------------
// helpers
// ---------------------------------------------------------------------------
__device__ __forceinline__ uint32_t smem_u32(const void* p) {
    uint32_t a;
    asm("{ .reg .u64 t; cvta.to.shared.u64 t, %1; cvt.u32.u64 %0, t; }"
        : "=r"(a) : "l"(p));
    return a;
}
__device__ __forceinline__ void cp16(uint32_t sdst, const void* gsrc) {
    asm volatile("cp.async.cg.shared.global [%0], [%1], 16;"
                 :: "r"(sdst), "l"(gsrc));
}
__device__ __forceinline__ void cp_commit() {
    asm volatile("cp.async.commit_group;");
}
template <int N>
__device__ __forceinline__ void cp_wait() {
    asm volatile("cp.async.wait_group %0;" :: "n"(N));
}
__device__ __forceinline__ void mma_bf16(float& c0, float& c1, float& c2, float& c3,
                                         uint32_t a0, uint32_t a1, uint32_t a2, uint32_t a3,
                                         uint32_t b0, uint32_t b1) {
    asm volatile(
        "mma.sync.aligned.m16n8k16.row.col.f32.bf16.bf16.f32 "
        "{%0,%1,%2,%3}, {%4,%5,%6,%7}, {%8,%9}, {%0,%1,%2,%3};"
        : "+f"(c0), "+f"(c1), "+f"(c2), "+f"(c3)
        : "r"(a0), "r"(a1), "r"(a2), "r"(a3), "r"(b0), "r"(b1));
}
// pack two fp32 into bf16x2: low half = lo, high half = hi
__device__ __forceinline__ uint32_t pack_bf16x2(float lo, float hi) {
    uint32_t r;
    asm("cvt.rn.bf16x2.f32 %0, %1, %2;" : "=r"(r) : "f"(hi), "f"(lo));
    return r;
}

// ---------------------------------------------------------------------------
// fp32 -> bf16 hi/lo split (vectorized x4)
// ---------------------------------------------------------------------------
__global__ __launch_bounds__(256) void split_kernel(
    const float* __restrict__ x, __nv_bfloat16* __restrict__ hi,
    __nv_bfloat16* __restrict__ lo, int n4)
{
    int i = blockIdx.x * blockDim.x + threadIdx.x;
    if (i >= n4) return;
    float4 v = ((const float4*)x)[i];
    __nv_bfloat16 h0 = __float2bfloat16_rn(v.x);
    __nv_bfloat16 h1 = __float2bfloat16_rn(v.y);
    __nv_bfloat16 h2 = __float2bfloat16_rn(v.z);
    __nv_bfloat16 h3 = __float2bfloat16_rn(v.w);
    __nv_bfloat16 l0 = __float2bfloat16_rn(v.x - __bfloat162float(h0));
    __nv_bfloat16 l1 = __float2bfloat16_rn(v.y - __bfloat162float(h1));
    __nv_bfloat16 l2 = __float2bfloat16_rn(v.z - __bfloat162float(h2));
    __nv_bfloat16 l3 = __float2bfloat16_rn(v.w - __bfloat162float(h3));
    __nv_bfloat162* hp = (__nv_bfloat162*)(hi + (size_t)i * 4);
    __nv_bfloat162* lp = (__nv_bfloat162*)(lo + (size_t)i * 4);
    hp[0] = __nv_bfloat162(h0, h1);
    hp[1] = __nv_bfloat162(h2, h3);
    lp[0] = __nv_bfloat162(l0, l1);
    lp[1] = __nv_bfloat162(l2, l3);
}

// ---------------------------------------------------------------------------
// mma.sync GEMM: C[M,N] = A[M,K] @ W[N,K]^T + bias (fp32 via bf16 hi/lo 3-term)
// CTA 128x128, BK=32, 8 warps (2M x 4N), warp tile 64x32, cp.async 2-stage.
// MODE 0: C fp32 row-major.
// MODE 2: bf16 hi/lo outputs in head layout [B,H,S,DH]   (for Q and K)
// MODE 3: bf16 hi/lo outputs transposed    [B,H,DH,S]    (for V)
// ---------------------------------------------------------------------------
#define BK 32
#define NKC (DD / BK)
#define TSTRIDE 40
#define TILE_B (128 * TSTRIDE * 2)
#define STAGE_B (4 * TILE_B)
#define GEMM_SMEM (2 * STAGE_B)

__device__ __forceinline__ void load_tile_async(
    uint32_t sbase, const __nv_bfloat16* __restrict__ src,
    int row_base, int k0, int tid)
{
#pragma unroll
    for (int p = 0; p < 2; p++) {
        const int i = p * 256 + tid;
        const int r = i >> 2;
        const int c = i & 3;
        cp16(sbase + r * (TSTRIDE * 2) + c * 16,
             src + (size_t)(row_base + r) * DD + k0 + c * 8);
    }
}

template <int MODE>
__global__ __launch_bounds__(256) void mma_gemm_kernel(
    const __nv_bfloat16* __restrict__ Ahi, const __nv_bfloat16* __restrict__ Alo,
    const __nv_bfloat16* __restrict__ Whi, const __nv_bfloat16* __restrict__ Wlo,
    const float* __restrict__ bias, float* __restrict__ C,
    __nv_bfloat16* __restrict__ Ohi, __nv_bfloat16* __restrict__ Olo)
{
    extern __shared__ char sm[];
    const uint32_t sb = smem_u32(sm);
    const int tid = threadIdx.x;
    const int wid = tid >> 5;
    const int lid = tid & 31;
    const int g = lid >> 2;
    const int t = lid & 3;
    const int bm = blockIdx.y * 128;
    const int bn = blockIdx.x * 128;
    const int wm = (wid & 1) * 64;
    const int wn = (wid >> 1) * 32;

    float acc[4][4][4];
#pragma unroll
    for (int mt = 0; mt < 4; mt++)
#pragma unroll
        for (int nt = 0; nt < 4; nt++)
#pragma unroll
            for (int r = 0; r < 4; r++) acc[mt][nt][r] = 0.0f;

    {
        load_tile_async(sb + 0 * TILE_B, Ahi, bm, 0, tid);
        load_tile_async(sb + 1 * TILE_B, Alo, bm, 0, tid);
        load_tile_async(sb + 2 * TILE_B, Whi, bn, 0, tid);
        load_tile_async(sb + 3 * TILE_B, Wlo, bn, 0, tid);
        cp_commit();
    }

    for (int kc = 0; kc < NKC; kc++) {
        const int s = kc & 1;
        if (kc + 1 < NKC) {
            const uint32_t sn = sb + (s ^ 1) * STAGE_B;
            const int k0 = (kc + 1) * BK;
            load_tile_async(sn + 0 * TILE_B, Ahi, bm, k0, tid);
            load_tile_async(sn + 1 * TILE_B, Alo, bm, k0, tid);
            load_tile_async(sn + 2 * TILE_B, Whi, bn, k0, tid);
            load_tile_async(sn + 3 * TILE_B, Wlo, bn, k0, tid);
            cp_commit();
            cp_wait<1>();
        } else {
            cp_wait<0>();
        }
        __syncthreads();

        const char* stg = sm + s * STAGE_B;
        const char* tAhi = stg + 0 * TILE_B;
        const char* tAlo = stg + 1 * TILE_B;
        const char* tWhi = stg + 2 * TILE_B;
        const char* tWlo = stg + 3 * TILE_B;

#pragma unroll
        for (int k16 = 0; k16 < 2; k16++) {
            const int k0 = k16 * 16;
            uint32_t ah[4][4], al[4][4], bh[4][2], bl[4][2];
#pragma unroll
            for (int mt = 0; mt < 4; mt++) {
                const int r0 = wm + mt * 16 + g;
                const int cA = k0 + 2 * t;
                ah[mt][0] = *(const uint32_t*)(tAhi + ((r0)     * TSTRIDE + cA)     * 2);
                ah[mt][1] = *(const uint32_t*)(tAhi + ((r0 + 8) * TSTRIDE + cA)     * 2);
                ah[mt][2] = *(const uint32_t*)(tAhi + ((r0)     * TSTRIDE + cA + 8) * 2);
                ah[mt][3] = *(const uint32_t*)(tAhi + ((r0 + 8) * TSTRIDE + cA + 8) * 2);
                al[mt][0] = *(const uint32_t*)(tAlo + ((r0)     * TSTRIDE + cA)     * 2);
                al[mt][1] = *(const uint32_t*)(tAlo + ((r0 + 8) * TSTRIDE + cA)     * 2);
                al[mt][2] = *(const uint32_t*)(tAlo + ((r0)     * TSTRIDE + cA + 8) * 2);
                al[mt][3] = *(const uint32_t*)(tAlo + ((r0 + 8) * TSTRIDE + cA + 8) * 2);
            }
#pragma unroll
            for (int nt = 0; nt < 4; nt++) {
                const int nr = wn + nt * 8 + g;
                const int cB = k0 + 2 * t;
                bh[nt][0] = *(const uint32_t*)(tWhi + (nr * TSTRIDE + cB)     * 2);
                bh[nt][1] = *(const uint32_t*)(tWhi + (nr * TSTRIDE + cB + 8) * 2);
                bl[nt][0] = *(const uint32_t*)(tWlo + (nr * TSTRIDE + cB)     * 2);
                bl[nt][1] = *(const uint32_t*)(tWlo + (nr * TSTRIDE + cB + 8) * 2);
            }
#pragma unroll
            for (int mt = 0; mt < 4; mt++)
#pragma unroll
                for (int nt = 0; nt < 4; nt++) {
                    float* c = acc[mt][nt];
                    mma_bf16(c[0], c[1], c[2], c[3],
                             ah[mt][0], ah[mt][1], ah[mt][2], ah[mt][3],
                             bh[nt][0], bh[nt][1]);
                    mma_bf16(c[0], c[1], c[2], c[3],
                             ah[mt][0], ah[mt][1], ah[mt][2], ah[mt][3],
                             bl[nt][0], bl[nt][1]);
                    mma_bf16(c[0], c[1], c[2], c[3],
                             al[mt][0], al[mt][1], al[mt][2], al[mt][3],
                             bh[nt][0], bh[nt][1]);
                }
        }
        __syncthreads();
    }

    // epilogue
#pragma unroll
    for (int mt = 0; mt < 4; mt++) {
#pragma unroll
        for (int nt = 0; nt < 4; nt++) {
            const float* c = acc[mt][nt];
            const int n0 = bn + wn + nt * 8 + 2 * t;
            const float bia0 = __ldg(&bias[n0]);
            const float bia1 = __ldg(&bias[n0 + 1]);
#pragma unroll
            for (int half = 0; half < 2; half++) {
                const int m = bm + wm + mt * 16 + g + half * 8;
                const float v0 = c[half * 2 + 0] + bia0;
                const float v1 = c[half * 2 + 1] + bia1;
                if (MODE == 0) {
                    C[(size_t)m * DD + n0] = v0;
                    C[(size_t)m * DD + n0 + 1] = v1;
                } else {
                    const int bidx = m >> 11;
                    const int sidx = m & (SS - 1);
                    const int h0 = n0 >> 6;
                    const int dh = n0 & (DHH - 1);
                    __nv_bfloat16 h_0 = __float2bfloat16_rn(v0);
                    __nv_bfloat16 h_1 = __float2bfloat16_rn(v1);
                    __nv_bfloat16 l_0 = __float2bfloat16_rn(v0 - __bfloat162float(h_0));
                    __nv_bfloat16 l_1 = __float2bfloat16_rn(v1 - __bfloat162float(h_1));
                    if (MODE == 2) {
                        const size_t idx = (((size_t)bidx * HH + h0) * SS + sidx) * DHH + dh;
                        *(__nv_bfloat162*)(Ohi + idx) = __nv_bfloat162(h_0, h_1);
                        *(__nv_bfloat162*)(Olo + idx) = __nv_bfloat162(l_0, l_1);
                    } else {  // MODE 3: transposed [B,H,DH,S]
                        const size_t idx = (((size_t)bidx * HH + h0) * DHH + dh) * SS + sidx;
                        Ohi[idx] = h_0;
                        Ohi[idx + SS] = h_1;
                        Olo[idx] = l_0;
                        Olo[idx + SS] = l_1;
                    }
                }
            }
        }
    }
}

// ---------------------------------------------------------------------------
// Tensor-core flash attention (bf16 hi/lo 3-term, fp32 softmax)
// CTA: 128 thr / 4 warps, Bq = Bc = 64, each warp owns 16 q rows.
// K tiles  [64 key][64 dh]  from g_khi/g_klo  (head layout rows)
// VT tiles [64 dh ][64 key] from g_vthi/g_vtlo (transposed layout rows)
// ---------------------------------------------------------------------------
#define KSTR 72                       // bf16 elements per smem row
#define FTILE_B (64 * KSTR * 2)       // 9216 bytes
#define FSTAGE_B (4 * FTILE_B)        // Khi,Klo,VThi,VTlo = 36864
#define FLASH_SMEM (2 * FSTAGE_B)     // 73728

__global__ __launch_bounds__(128) void flash_tc_kernel(
    const __nv_bfloat16* __restrict__ Qhi, const __nv_bfloat16* __restrict__ Qlo,
    const __nv_bfloat16* __restrict__ Khi, const __nv_bfloat16* __restrict__ Klo,
    const __nv_bfloat16* __restrict__ VThi, const __nv_bfloat16* __restrict__ VTlo,
    float* __restrict__ ctx)
{
    extern __shared__ char sm[];
    const uint32_t sb = smem_u32(sm);
    const int tid = threadIdx.x;
    const int wid = tid >> 5;
    const int lid = tid & 31;
    const int g = lid >> 2;
    const int t = lid & 3;
    const int qb = gridDim.x - 1 - blockIdx.x;   // heavy CTAs first
    const int bh = blockIdx.y;

    const size_t hoff = (size_t)bh * SS * DHH;   // same for head & transposed
    const __nv_bfloat16* qhi = Qhi + hoff;
    const __nv_bfloat16* qlo = Qlo + hoff;
    const __nv_bfloat16* khi = Khi + hoff;
    const __nv_bfloat16* klo = Klo + hoff;
    const __nv_bfloat16* vthi = VThi + hoff;
    const __nv_bfloat16* vtlo = VTlo + hoff;

    const int qrow0 = qb * 64 + wid * 16;

    // Q fragments (register resident): 4 k16-steps x (a0..a3) x hi/lo
    uint32_t qh[4][4], ql[4][4];
#pragma unroll
    for (int s = 0; s < 4; s++) {
        const int cA = s * 16 + 2 * t;
        qh[s][0] = *(const uint32_t*)(qhi + (size_t)(qrow0 + g)     * DHH + cA);
        qh[s][1] = *(const uint32_t*)(qhi + (size_t)(qrow0 + g + 8) * DHH + cA);
        qh[s][2] = *(const uint32_t*)(qhi + (size_t)(qrow0 + g)     * DHH + cA + 8);
        qh[s][3] = *(const uint32_t*)(qhi + (size_t)(qrow0 + g + 8) * DHH + cA + 8);
        ql[s][0] = *(const uint32_t*)(qlo + (size_t)(qrow0 + g)     * DHH + cA);
        ql[s][1] = *(const uint32_t*)(qlo + (size_t)(qrow0 + g + 8) * DHH + cA);
        ql[s][2] = *(const uint32_t*)(qlo + (size_t)(qrow0 + g)     * DHH + cA + 8);
        ql[s][3] = *(const uint32_t*)(qlo + (size_t)(qrow0 + g + 8) * DHH + cA + 8);
    }

    float oa[8][4];
#pragma unroll
    for (int j = 0; j < 8; j++)
#pragma unroll
        for (int r = 0; r < 4; r++) oa[j][r] = 0.0f;
    float mrun0 = -INFINITY, mrun1 = -INFINITY, lrun0 = 0.0f, lrun1 = 0.0f;

    // kv tile loader: 16 cp16 per thread (4 per tile)
    auto load_kv = [&](int jb, int stage) {
        const uint32_t s0 = sb + stage * FSTAGE_B;
        const int kb = jb * 64;
#pragma unroll
        for (int p = 0; p < 4; p++) {
            const int i = p * 128 + tid;   // 0..511
            const int r = i >> 3;          // 0..63
            const int c = i & 7;           // 16B unit
            const uint32_t d = r * (KSTR * 2) + c * 16;
            cp16(s0 + 0 * FTILE_B + d, khi  + (size_t)(kb + r) * DHH + c * 8);
            cp16(s0 + 1 * FTILE_B + d, klo  + (size_t)(kb + r) * DHH + c * 8);
            cp16(s0 + 2 * FTILE_B + d, vthi + (size_t)r * SS + kb + c * 8);
            cp16(s0 + 3 * FTILE_B + d, vtlo + (size_t)r * SS + kb + c * 8);
        }
    };

    load_kv(0, 0);
    cp_commit();

    const float scale = 0.125f;

    for (int jb = 0; jb <= qb; jb++) {
        const int s = jb & 1;
        if (jb < qb) {
            load_kv(jb + 1, s ^ 1);
            cp_commit();
            cp_wait<1>();
        } else {
            cp_wait<0>();
        }
        __syncthreads();

        const char* stg = sm + s * FSTAGE_B;
        const char* tKhi = stg + 0 * FTILE_B;
        const char* tKlo = stg + 1 * FTILE_B;
        const char* tVhi = stg + 2 * FTILE_B;
        const char* tVlo = stg + 3 * FTILE_B;

        // ---- S = Q K^T ----
        float sacc[8][4];
#pragma unroll
        for (int j = 0; j < 8; j++)
#pragma unroll
            for (int r = 0; r < 4; r++) sacc[j][r] = 0.0f;

#pragma unroll
        for (int j = 0; j < 8; j++) {
            const int nr = j * 8 + g;
#pragma unroll
            for (int ks = 0; ks < 4; ks++) {
                const int cB = ks * 16 + 2 * t;
                uint32_t bh0 = *(const uint32_t*)(tKhi + (nr * KSTR + cB)     * 2);
                uint32_t bh1 = *(const uint32_t*)(tKhi + (nr * KSTR + cB + 8) * 2);
                uint32_t bl0 = *(const uint32_t*)(tKlo + (nr * KSTR + cB)     * 2);
                uint32_t bl1 = *(const uint32_t*)(tKlo + (nr * KSTR + cB + 8) * 2);
                float* c = sacc[j];
                mma_bf16(c[0], c[1], c[2], c[3],
                         qh[ks][0], qh[ks][1], qh[ks][2], qh[ks][3], bh0, bh1);
                mma_bf16(c[0], c[1], c[2], c[3],
                         qh[ks][0], qh[ks][1], qh[ks][2], qh[ks][3], bl0, bl1);
                mma_bf16(c[0], c[1], c[2], c[3],
                         ql[ks][0], ql[ks][1], ql[ks][2], ql[ks][3], bh0, bh1);
            }
        }

        // ---- scale + causal mask ----
        const int qg0 = qrow0 + g;
        const int qg1 = qrow0 + g + 8;
        if (jb == qb) {
            const int kbase = jb * 64;
#pragma unroll
            for (int j = 0; j < 8; j++) {
                const int c0 = kbase + j * 8 + 2 * t;
                const int c1 = c0 + 1;
                sacc[j][0] = (c0 > qg0) ? -1e30f : sacc[j][0] * scale;
                sacc[j][1] = (c1 > qg0) ? -1e30f : sacc[j][1] * scale;
                sacc[j][2] = (c0 > qg1) ? -1e30f : sacc[j][2] * scale;
                sacc[j][3] = (c1 > qg1) ? -1e30f : sacc[j][3] * scale;
            }
        } else {
#pragma unroll
            for (int j = 0; j < 8; j++)
#pragma unroll
                for (int r = 0; r < 4; r++) sacc[j][r] *= scale;
        }

        // ---- online softmax (rows g and g+8) ----
        float mt0 = -INFINITY, mt1 = -INFINITY;
#pragma unroll
        for (int j = 0; j < 8; j++) {
            mt0 = fmaxf(mt0, fmaxf(sacc[j][0], sacc[j][1]));
            mt1 = fmaxf(mt1, fmaxf(sacc[j][2], sacc[j][3]));
        }
        mt0 = fmaxf(mt0, __shfl_xor_sync(0xffffffffu, mt0, 1));
        mt0 = fmaxf(mt0, __shfl_xor_sync(0xffffffffu, mt0, 2));
        mt1 = fmaxf(mt1, __shfl_xor_sync(0xffffffffu, mt1, 1));
        mt1 = fmaxf(mt1, __shfl_xor_sync(0xffffffffu, mt1, 2));
        const float mn0 = fmaxf(mrun0, mt0);
        const float mn1 = fmaxf(mrun1, mt1);
        const float al0 = __expf(mrun0 - mn0);
        const float al1 = __expf(mrun1 - mn1);
        float rs0 = 0.0f, rs1 = 0.0f;
#pragma unroll
        for (int j = 0; j < 8; j++) {
            sacc[j][0] = __expf(sacc[j][0] - mn0);
            sacc[j][1] = __expf(sacc[j][1] - mn0);
            sacc[j][2] = __expf(sacc[j][2] - mn1);
            sacc[j][3] = __expf(sacc[j][3] - mn1);
            rs0 += sacc[j][0] + sacc[j][1];
            rs1 += sacc[j][2] + sacc[j][3];
        }
        rs0 += __shfl_xor_sync(0xffffffffu, rs0, 1);
        rs0 += __shfl_xor_sync(0xffffffffu, rs0, 2);
        rs1 += __shfl_xor_sync(0xffffffffu, rs1, 1);
        rs1 += __shfl_xor_sync(0xffffffffu, rs1, 2);
        lrun0 = al0 * lrun0 + rs0;
        lrun1 = al1 * lrun1 + rs1;
        mrun0 = mn0;
        mrun1 = mn1;
#pragma unroll
        for (int j = 0; j < 8; j++) {
            oa[j][0] *= al0;
            oa[j][1] *= al0;
            oa[j][2] *= al1;
            oa[j][3] *= al1;
        }

        // ---- O += P V ----
#pragma unroll
        for (int ks = 0; ks < 4; ks++) {
            const int j0 = 2 * ks, j1 = 2 * ks + 1;
            uint32_t pah[4], pal[4];
            {
                uint32_t h;
                __nv_bfloat162 hb;
                h = pack_bf16x2(sacc[j0][0], sacc[j0][1]);
                hb = *(__nv_bfloat162*)&h;
                pah[0] = h;
                pal[0] = pack_bf16x2(sacc[j0][0] - __bfloat162float(hb.x),
                                     sacc[j0][1] - __bfloat162float(hb.y));
                h = pack_bf16x2(sacc[j0][2], sacc[j0][3]);
                hb = *(__nv_bfloat162*)&h;
                pah[1] = h;
                pal[1] = pack_bf16x2(sacc[j0][2] - __bfloat162float(hb.x),
                                     sacc[j0][3] - __bfloat162float(hb.y));
                h = pack_bf16x2(sacc[j1][0], sacc[j1][1]);
                hb = *(__nv_bfloat162*)&h;
                pah[2] = h;
                pal[2] = pack_bf16x2(sacc[j1][0] - __bfloat162float(hb.x),
                                     sacc[j1][1] - __bfloat162float(hb.y));
                h = pack_bf16x2(sacc[j1][2], sacc[j1][3]);
                hb = *(__nv_bfloat162*)&h;
                pah[3] = h;
                pal[3] = pack_bf16x2(sacc[j1][2] - __bfloat162float(hb.x),
                                     sacc[j1][3] - __bfloat162float(hb.y));
            }
#pragma unroll
            for (int jd = 0; jd < 8; jd++) {
                const int nr = jd * 8 + g;
                const int cB = ks * 16 + 2 * t;
                uint32_t vh0 = *(const uint32_t*)(tVhi + (nr * KSTR + cB)     * 2);
                uint32_t vh1 = *(const uint32_t*)(tVhi + (nr * KSTR + cB + 8) * 2);
                uint32_t vl0 = *(const uint32_t*)(tVlo + (nr * KSTR + cB)     * 2);
                uint32_t vl1 = *(const uint32_t*)(tVlo + (nr * KSTR + cB + 8) * 2);
                float* c = oa[jd];
                mma_bf16(c[0], c[1], c[2], c[3],
                         pah[0], pah[1], pah[2], pah[3], vh0, vh1);
                mma_bf16(c[0], c[1], c[2], c[3],
                         pah[0], pah[1], pah[2], pah[3], vl0, vl1);
                mma_bf16(c[0], c[1], c[2], c[3],
                         pal[0], pal[1], pal[2], pal[3], vh0, vh1);
            }
        }
        __syncthreads();
    }

    // ---- finalize: ctx[B,S,D] ----
    const int b = bh >> 4;
    const int h = bh & 15;
    const float inv0 = 1.0f / lrun0;
    const float inv1 = 1.0f / lrun1;
#pragma unroll
    for (int jd = 0; jd < 8; jd++) {
        const int dh = jd * 8 + 2 * t;
        float2 r0 = make_float2(oa[jd][0] * inv0, oa[jd][1] * inv0);
        float2 r1 = make_float2(oa[jd][2] * inv1, oa[jd][3] * inv1);
        *(float2*)(ctx + ((size_t)b * SS + qrow0 + g)     * DD + h * DHH + dh) = r0;
        *(float2*)(ctx + ((size_t)b * SS + qrow0 + g + 8) * DD + h * DHH + dh) = r1;
    }
}

// ---------------------------------------------------------------------------
// Launch
// ---------------------------------------------------------------------------
extern "C" void kernel_launch(void* const* d_in, const int* in_sizes, int n_in,
                              void* d_out, int out_size)
{
    const float* query = (const float*)d_in[0];
    const float* key_i = (const float*)d_in[1];
    const float* value = (const float*)d_in[2];
    const float* Wq = (const float*)d_in[4];
    const float* bq = (const float*)d_in[5];
    const float* Wk = (const float*)d_in[6];
    const float* bk = (const float*)d_in[7];
    const float* Wv = (const float*)d_in[8];
    const float* bv = (const float*)d_in[9];
    const float* Wo = (const float*)d_in[10];
    const float* bo = (const float*)d_in[11];
    float* out = (float*)d_out;

    float* ctx;
    __nv_bfloat16 *xhi, *xlo, *whi, *wlo;
    __nv_bfloat16 *qhi, *qlo, *khi, *klo, *vthi, *vtlo;
    cudaGetSymbolAddress((void**)&ctx, g_ctx);
    cudaGetSymbolAddress((void**)&xhi, g_xhi);
    cudaGetSymbolAddress((void**)&xlo, g_xlo);
    cudaGetSymbolAddress((void**)&whi, g_whi);
    cudaGetSymbolAddress((void**)&wlo, g_wlo);
    cudaGetSymbolAddress((void**)&qhi, g_qhi);
    cudaGetSymbolAddress((void**)&qlo, g_qlo);
    cudaGetSymbolAddress((void**)&khi, g_khi);
    cudaGetSymbolAddress((void**)&klo, g_klo);
    cudaGetSymbolAddress((void**)&vthi, g_vthi);
    cudaGetSymbolAddress((void**)&vtlo, g_vtlo);

    const int M = BB * SS;
    const int nX4 = M * DD / 4;
    const int nW4 = DD * DD / 4;
    dim3 sgX((nX4 + 255) / 256), sgW((nW4 + 255) / 256);
    dim3 ggrid(DD / 128, M / 128);

    cudaFuncSetAttribute(mma_gemm_kernel<0>,
                         cudaFuncAttributeMaxDynamicSharedMemorySize, GEMM_SMEM);
    cudaFuncSetAttribute(mma_gemm_kernel<2>,
                         cudaFuncAttributeMaxDynamicSharedMemorySize, GEMM_SMEM);
    cudaFuncSetAttribute(mma_gemm_kernel<3>,
                         cudaFuncAttributeMaxDynamicSharedMemorySize, GEMM_SMEM);
    cudaFuncSetAttribute(flash_tc_kernel,
                         cudaFuncAttributeMaxDynamicSharedMemorySize, FLASH_SMEM);

    // Q projection -> bf16 hi/lo head layout
    split_kernel<<<sgX, 256>>>(query, xhi, xlo, nX4);
    split_kernel<<<sgW, 256>>>(Wq, whi, wlo, nW4);
    mma_gemm_kernel<2><<<ggrid, 256, GEMM_SMEM>>>(xhi, xlo, whi, wlo, bq,
                                                  nullptr, qhi, qlo);
    // K projection
    split_kernel<<<sgX, 256>>>(key_i, xhi, xlo, nX4);
    split_kernel<<<sgW, 256>>>(Wk, whi, wlo, nW4);
    mma_gemm_kernel<2><<<ggrid, 256, GEMM_SMEM>>>(xhi, xlo, whi, wlo, bk,
                                                  nullptr, khi, klo);
    // V projection -> transposed bf16 hi/lo
    split_kernel<<<sgX, 256>>>(value, xhi, xlo, nX4);
    split_kernel<<<sgW, 256>>>(Wv, whi, wlo, nW4);
    mma_gemm_kernel<3><<<ggrid, 256, GEMM_SMEM>>>(xhi, xlo, whi, wlo, bv,
                                                  nullptr, vthi, vtlo);

    // tensor-core flash attention
    flash_tc_kernel<<<dim3(SS / 64, BB * HH), 128, FLASH_SMEM>>>(
        qhi, qlo, khi, klo, vthi, vtlo, ctx);

    // O projection
    split_kernel<<<sgX, 256>>>(ctx, xhi, xlo, nX4);
    split_kernel<<<sgW, 256>>>(Wo, whi, wlo, nW4);
    mma_gemm_kernel<0><<<ggrid, 256, GEMM_SMEM>>>(xhi, xlo, whi, wlo, bo,
                                                  out, nullptr, nullptr);
}